// round 15
// baseline (speedup 1.0000x reference)
#include <cuda_runtime.h>
#include <cuda_fp16.h>
#include <math_constants.h>
#include <cstdint>

#define N_PIX   16384
#define K_CODES 8192
#define D_DIM   256

// ---------------- scratch ----------------
__device__ float g_x2[N_PIX];
__device__ float g_c2[K_CODES];
__device__ unsigned long long g_argmin[N_PIX];
__device__ __half g_xs[2][N_PIX * D_DIM];                 // x hi/lo fp16
__device__ __half g_cs[2][K_CODES * D_DIM];               // cb hi/lo fp16
__device__ __half g_cbT[(size_t)D_DIM * K_CODES];         // cbT hi fp16
__device__ __half g_ench[(size_t)N_PIX * K_CODES];        // encodings hi fp16

// ---------------- PTX helpers (plain sm_80+) ----------------
__device__ __forceinline__ uint32_t smem_u32(const void* p) {
    uint32_t a;
    asm("{ .reg .u64 t; cvta.to.shared.u64 t, %1; cvt.u32.u64 %0, t; }" : "=r"(a) : "l"(p));
    return a;
}
#define CP16(sa, ga)  asm volatile("cp.async.cg.shared.global [%0], [%1], 16;" :: "r"(sa), "l"(ga) : "memory")
#define CPCOMMIT()    asm volatile("cp.async.commit_group;" ::: "memory")
#define CPWAIT0()     asm volatile("cp.async.wait_group 0;" ::: "memory")

#define LDSM4(r0, r1, r2, r3, a) asm volatile(                                   \
    "ldmatrix.sync.aligned.m8n8.x4.shared.b16 {%0,%1,%2,%3}, [%4];"              \
    : "=r"(r0), "=r"(r1), "=r"(r2), "=r"(r3) : "r"(a))

#define MMA(c, a, b) asm volatile(                                               \
    "mma.sync.aligned.m16n8k16.row.col.f32.f16.f16.f32 "                         \
    "{%0,%1,%2,%3}, {%4,%5,%6,%7}, {%8,%9}, {%0,%1,%2,%3};"                      \
    : "+f"((c)[0]), "+f"((c)[1]), "+f"((c)[2]), "+f"((c)[3])                     \
    : "r"((a)[0]), "r"((a)[1]), "r"((a)[2]), "r"((a)[3]),                        \
      "r"((b)[0]), "r"((b)[1]))

#define ROWB 80          // row stride 80B for 32-fp16 rows (conflict-free ldmatrix)
#define TILEB 10240      // one 128x32 fp16 tile
#define STAGE1 40960     // Ah|Am|Bh|Bm per stage (gemm1, 128x128 tile)
#define ROWB2 144        // row stride 144B for 64-fp16 rows (gemm2)
#define TILE2A 18432     // 128 x 64 fp16 (A tile, gemm2)
#define TILE2B 36864     // 256 x 64 fp16 (B tile, gemm2)
#define STAGE2 55296     // A|B per stage (gemm2)

__device__ __forceinline__ uint32_t h2u(__half2 h) { return *reinterpret_cast<uint32_t*>(&h); }

// ---------------- prepass: fp16 hi/lo split + row norm (+argmin init for x) ----------------
__global__ __launch_bounds__(256)
void k_prep(const float* __restrict__ src, int which) {
    const int row = blockIdx.x * 8 + (threadIdx.x >> 5);
    const int lane = threadIdx.x & 31;
    const float* p = src + (size_t)row * D_DIM + lane * 8;
    float4 v0 = ((const float4*)p)[0], v1 = ((const float4*)p)[1];
    float f[8] = {v0.x, v0.y, v0.z, v0.w, v1.x, v1.y, v1.z, v1.w};
    __half hi[8]; float s = 0.f;
    uint32_t hw[4], mw[4];
#pragma unroll
    for (int t = 0; t < 8; t++) { hi[t] = __float2half_rn(f[t]); s = fmaf(f[t], f[t], s); }
#pragma unroll
    for (int t = 0; t < 4; t++) {
        hw[t] = h2u(__halves2half2(hi[2*t], hi[2*t+1]));
        mw[t] = h2u(__floats2half2_rn(f[2*t]   - __half2float(hi[2*t]),
                                      f[2*t+1] - __half2float(hi[2*t+1])));
    }
    size_t o = ((size_t)row * D_DIM + lane * 8);
    __half* H = which ? g_cs[0] : g_xs[0];
    __half* M = which ? g_cs[1] : g_xs[1];
    *(uint4*)(H + o) = make_uint4(hw[0], hw[1], hw[2], hw[3]);
    *(uint4*)(M + o) = make_uint4(mw[0], mw[1], mw[2], mw[3]);
#pragma unroll
    for (int o2 = 16; o2 > 0; o2 >>= 1) s += __shfl_xor_sync(0xffffffffu, s, o2);
    if (lane == 0) {
        (which ? g_c2 : g_x2)[row] = s;
        if (!which) g_argmin[row] = 0xFFFFFFFFFFFFFFFFULL;
    }
}

__global__ void k_transpose(const float* __restrict__ cb) {
    __shared__ float t[32][33];
    int k0 = blockIdx.x * 32, d0 = blockIdx.y * 32;
    int tx = threadIdx.x, ty = threadIdx.y;  // 32x8
#pragma unroll
    for (int i = 0; i < 32; i += 8)
        t[ty + i][tx] = cb[(size_t)(k0 + ty + i) * D_DIM + d0 + tx];
    __syncthreads();
#pragma unroll
    for (int i = 0; i < 32; i += 8)
        g_cbT[(size_t)(d0 + ty + i) * K_CODES + k0 + tx] = __float2half_rn(t[tx][ty + i]);
}

// ---------------- GEMM1: 128x128 tile, 8 warps (warp 64x32), 3-combo fp16 split ----------------
// dyn smem: 2 stages x [Ah|Am|Bh|Bm] x 10240B = 81920B -> 2 CTAs/SM
// Dead stage buffers recycled as smem noise cache:
//   buf0 <- noise rows 0..79 (prefetched during last MMA stage)
//   buf1 <- noise rows 80..127 (prefetched during epilogue pass A)
__global__ __launch_bounds__(256)
void k_gemm1(const float* __restrict__ noise, float* __restrict__ logits) {
    extern __shared__ __align__(16) char dyn[];
    __shared__ float x2s[128], c2s[128];
    __shared__ unsigned long long sMin[128];
    const uint32_t db = smem_u32(dyn);

    const int tid = threadIdx.x, lane = tid & 31, wid = tid >> 5;
    const int wm = wid >> 2, wn = wid & 3;
    const int rowBase = blockIdx.y << 7, colBase = blockIdx.x << 7;

    if (tid < 128) {
        x2s[tid] = g_x2[rowBase + tid];
        c2s[tid] = g_c2[colBase + tid];
        sMin[tid] = 0xFFFFFFFFFFFFFFFFULL;
    }

    float acc[4][4][4];
#pragma unroll
    for (int a = 0; a < 4; a++)
#pragma unroll
        for (int b = 0; b < 4; b++)
#pragma unroll
            for (int c = 0; c < 4; c++) acc[a][b][c] = 0.f;

    const int r = tid >> 1, h = tid & 1;
    const uint32_t so = (uint32_t)(r * ROWB + h * 32);
    const float* ntile = noise + (size_t)rowBase * K_CODES + colBase;

    auto load_stage = [&](int s, int k0) {
        uint32_t base = db + s * STAGE1;
        size_t ao = (size_t)(rowBase + r) * D_DIM + k0 + h * 16;
        size_t bo = (size_t)(colBase + r) * D_DIM + k0 + h * 16;
        CP16(base + so, g_xs[0] + ao);                 CP16(base + so + 16, g_xs[0] + ao + 8);
        CP16(base + TILEB + so, g_xs[1] + ao);         CP16(base + TILEB + so + 16, g_xs[1] + ao + 8);
        CP16(base + 2*TILEB + so, g_cs[0] + bo);       CP16(base + 2*TILEB + so + 16, g_cs[0] + bo + 8);
        CP16(base + 3*TILEB + so, g_cs[1] + bo);       CP16(base + 3*TILEB + so + 16, g_cs[1] + bo + 8);
        CPCOMMIT();
    };

    load_stage(0, 0);
    for (int s = 0; s < 8; s++) {
        CPWAIT0();
        __syncthreads();
        if (s + 1 < 8) {
            load_stage((s + 1) & 1, (s + 1) << 5);
        } else {
            // prefetch noise rows 0..79 into buf0 (free since mma(6)); 10x16B per thread
#pragma unroll
            for (int i = 0; i < 10; i++) {
                uint32_t o = (uint32_t)(i * 256 + tid) * 16;      // 0..40944
                uint32_t rr = o >> 9, cc = o & 511;               // row, byte-col
                CP16(db + o, (const char*)ntile + (size_t)rr * (K_CODES * 4) + cc);
            }
            CPCOMMIT();
        }
        uint32_t base = db + (s & 1) * STAGE1;
        const uint32_t aH = base, aM = base + TILEB;
        const uint32_t bH = base + 2*TILEB, bM = bH + TILEB;
#pragma unroll
        for (int kk = 0; kk < 2; kk++) {
            uint32_t ah[4][4], am[4][4], bh[4][2], bm[4][2];
#pragma unroll
            for (int mt = 0; mt < 4; mt++) {
                uint32_t off = (uint32_t)((wm * 64 + mt * 16 + (lane & 15)) * ROWB
                                          + ((lane >> 4) << 4) + kk * 32);
                LDSM4(ah[mt][0], ah[mt][1], ah[mt][2], ah[mt][3], aH + off);
                LDSM4(am[mt][0], am[mt][1], am[mt][2], am[mt][3], aM + off);
            }
#pragma unroll
            for (int n2 = 0; n2 < 2; n2++) {
                uint32_t off = (uint32_t)((wn * 32 + n2 * 16 + (lane & 7) + ((lane >> 4) << 3)) * ROWB
                                          + (((lane >> 3) & 1) << 4) + kk * 32);
                LDSM4(bh[2*n2][0], bh[2*n2][1], bh[2*n2+1][0], bh[2*n2+1][1], bH + off);
                LDSM4(bm[2*n2][0], bm[2*n2][1], bm[2*n2+1][0], bm[2*n2+1][1], bM + off);
            }
#pragma unroll
            for (int mt = 0; mt < 4; mt++)
#pragma unroll
                for (int nt = 0; nt < 4; nt++) {
                    MMA(acc[mt][nt], ah[mt], bh[nt]);
                    MMA(acc[mt][nt], am[mt], bh[nt]);
                    MMA(acc[mt][nt], ah[mt], bm[nt]);
                }
        }
    }

    CPWAIT0();          // my noise part1 arrived
    __syncthreads();    // everyone's part1 visible; everyone done with mma(7) -> buf1 free

    // prefetch noise rows 80..127 into buf1 (6x16B per thread), overlapped with pass A
#pragma unroll
    for (int i = 0; i < 6; i++) {
        uint32_t o = (uint32_t)(i * 256 + tid) * 16;              // 0..24560
        uint32_t rr = 80 + (o >> 9), cc = o & 511;
        CP16(db + STAGE1 + o, (const char*)ntile + (size_t)rr * (K_CODES * 4) + cc);
    }
    CPCOMMIT();

    // epilogue helper: process one (mt, hh) group reading noise from smem
    auto epi_group = [&](int mt, int hh) {
        const int rr = wm * 64 + mt * 16 + (lane >> 2) + hh * 8;
        const int grow = rowBase + rr;
        const float x2v = x2s[rr];
        unsigned long long best = 0xFFFFFFFFFFFFFFFFULL;
        float* lrow = logits + (size_t)grow * K_CODES + colBase;
        const uint32_t nbase = (rr < 80) ? (db + (uint32_t)rr * 512)
                                         : (db + STAGE1 + (uint32_t)(rr - 80) * 512);
#pragma unroll
        for (int nt = 0; nt < 4; nt++) {
            const int c = wn * 32 + nt * 8 + ((lane & 3) << 1);
            float2 nz;
            asm volatile("ld.shared.v2.f32 {%0,%1}, [%2];" : "=f"(nz.x), "=f"(nz.y)
                         : "r"(nbase + (uint32_t)c * 4));
            const float d0 = fmaf(-2.f, acc[mt][nt][hh * 2 + 0], x2v) + c2s[c];
            const float d1 = fmaf(-2.f, acc[mt][nt][hh * 2 + 1], x2v) + c2s[c + 1];
            *(float2*)(lrow + c) = make_float2(nz.x - d0, nz.y - d1);
            unsigned long long p0 = ((unsigned long long)__float_as_uint(d0) << 32) | (unsigned)(colBase + c);
            unsigned long long p1 = ((unsigned long long)__float_as_uint(d1) << 32) | (unsigned)(colBase + c + 1);
            if (p1 < p0) p0 = p1;
            if (p0 < best) best = p0;
        }
        atomicMin(&sMin[rr], best);
    };

    // pass A: rows < 80 -> wm==0: all mt ; wm==1: mt==0 only
    if (wm == 0) {
#pragma unroll
        for (int mt = 0; mt < 4; mt++) { epi_group(mt, 0); epi_group(mt, 1); }
    } else {
        epi_group(0, 0); epi_group(0, 1);
    }

    CPWAIT0();          // my noise part2 arrived
    __syncthreads();    // everyone's part2 visible

    // pass B: rows 80..127 -> wm==1, mt 1..3
    if (wm == 1) {
#pragma unroll
        for (int mt = 1; mt < 4; mt++) { epi_group(mt, 0); epi_group(mt, 1); }
    }

    __syncthreads();
    if (tid < 128) atomicMin(&g_argmin[rowBase + tid], sMin[tid]);
}

// ---------------- fused softmax: one block per row, row cached in smem ----------------
__global__ __launch_bounds__(256)
void k_softmax(float* __restrict__ logits) {
    __shared__ float buf[K_CODES];
    __shared__ float red[8];
    const int row = blockIdx.x, t = threadIdx.x, lane = t & 31, w = t >> 5;
    float* p = logits + (size_t)row * K_CODES;

    float m = -CUDART_INF_F;
    for (int c = t * 4; c < K_CODES; c += 1024) {
        float4 v = *(const float4*)(p + c);
        *(float4*)(buf + c) = v;
        m = fmaxf(m, fmaxf(fmaxf(v.x, v.y), fmaxf(v.z, v.w)));
    }
#pragma unroll
    for (int o = 16; o > 0; o >>= 1) m = fmaxf(m, __shfl_xor_sync(0xffffffffu, m, o));
    if (lane == 0) red[w] = m;
    __syncthreads();
    m = fmaxf(fmaxf(fmaxf(red[0], red[1]), fmaxf(red[2], red[3])),
              fmaxf(fmaxf(red[4], red[5]), fmaxf(red[6], red[7])));
    __syncthreads();

    float s = 0.f;
    for (int c = t * 4; c < K_CODES; c += 1024) {
        float4 v = *(const float4*)(buf + c);
        v.x = __expf(v.x - m); v.y = __expf(v.y - m);
        v.z = __expf(v.z - m); v.w = __expf(v.w - m);
        *(float4*)(buf + c) = v;
        s += (v.x + v.y) + (v.z + v.w);
    }
#pragma unroll
    for (int o = 16; o > 0; o >>= 1) s += __shfl_xor_sync(0xffffffffu, s, o);
    if (lane == 0) red[w] = s;
    __syncthreads();
    const float inv = 1.0f / (((red[0] + red[1]) + (red[2] + red[3]))
                            + ((red[4] + red[5]) + (red[6] + red[7])));
    for (int c = t * 4; c < K_CODES; c += 1024) {
        float4 v = *(const float4*)(buf + c);
        v.x *= inv; v.y *= inv; v.z *= inv; v.w *= inv;
        *(float4*)(p + c) = v;
        *(uint2*)(g_ench + (size_t)row * K_CODES + c) =
            make_uint2(h2u(__floats2half2_rn(v.x, v.y)), h2u(__floats2half2_rn(v.z, v.w)));
    }
}

// ---------------- GEMM2: quantized = enc_h @ cbT_h, full-D tile (128x256), A read once ----------------
// grid 128 CTAs (one per pixel block), 8 warps: warp grid 2x4, warp tile 64x64.
// dyn smem: 2 stages x [A(18432)|B(36864)] = 110592B ; 1 wave (128 <= 148 SMs).
__global__ __launch_bounds__(256, 1)
void k_gemm2(float* __restrict__ outq) {
    extern __shared__ __align__(16) char dyn[];
    const uint32_t db = smem_u32(dyn);

    const int tid = threadIdx.x, lane = tid & 31, wid = tid >> 5;
    const int wm = wid >> 2, wn = wid & 3;          // warp tile 64 x 64
    const int rowBase = blockIdx.x << 7;

    float acc[4][8][4];
#pragma unroll
    for (int a = 0; a < 4; a++)
#pragma unroll
        for (int b = 0; b < 8; b++)
#pragma unroll
            for (int c = 0; c < 4; c++) acc[a][b][c] = 0.f;

    const int r = tid >> 1, h = tid & 1;
    const uint32_t soA = (uint32_t)(r * ROWB2 + h * 64);
    const uint32_t soB = (uint32_t)tid * ROWB2;

    auto load_stage = [&](int buf, int k0) {
        uint32_t base = db + (uint32_t)buf * STAGE2;
        size_t ao = (size_t)(rowBase + r) * K_CODES + k0 + h * 32;
        CP16(base + soA,      g_ench + ao);      CP16(base + soA + 16, g_ench + ao + 8);
        CP16(base + soA + 32, g_ench + ao + 16); CP16(base + soA + 48, g_ench + ao + 24);
        uint32_t bb = base + TILE2A;
        size_t bo = (size_t)tid * K_CODES + k0;   // cbT row = d index (all 256)
#pragma unroll
        for (int j = 0; j < 8; j++)
            CP16(bb + soB + j * 16, g_cbT + bo + j * 8);
        CPCOMMIT();
    };

    load_stage(0, 0);
    for (int s = 0; s < 128; s++) {
        CPWAIT0();
        __syncthreads();
        if (s + 1 < 128) load_stage((s + 1) & 1, (s + 1) << 6);
        uint32_t base = db + (uint32_t)(s & 1) * STAGE2;
        const uint32_t aB = base, bB = base + TILE2A;
#pragma unroll
        for (int kk = 0; kk < 4; kk++) {
            uint32_t af[4][4], bf[8][2];
#pragma unroll
            for (int mt = 0; mt < 4; mt++) {
                uint32_t off = (uint32_t)((wm * 64 + mt * 16 + (lane & 15)) * ROWB2
                                          + ((lane >> 4) << 4) + kk * 32);
                LDSM4(af[mt][0], af[mt][1], af[mt][2], af[mt][3], aB + off);
            }
#pragma unroll
            for (int n4 = 0; n4 < 4; n4++) {
                uint32_t off = (uint32_t)((wn * 64 + n4 * 16 + (lane & 7) + ((lane >> 4) << 3)) * ROWB2
                                          + (((lane >> 3) & 1) << 4) + kk * 32);
                LDSM4(bf[2*n4][0], bf[2*n4][1], bf[2*n4+1][0], bf[2*n4+1][1], bB + off);
            }
#pragma unroll
            for (int mt = 0; mt < 4; mt++)
#pragma unroll
                for (int nt = 0; nt < 8; nt++)
                    MMA(acc[mt][nt], af[mt], bf[nt]);
        }
    }

#pragma unroll
    for (int mt = 0; mt < 4; mt++) {
#pragma unroll
        for (int hh = 0; hh < 2; hh++) {
            const int grow = rowBase + wm * 64 + mt * 16 + (lane >> 2) + hh * 8;
            float* orow = outq + (size_t)grow * D_DIM;
#pragma unroll
            for (int nt = 0; nt < 8; nt++) {
                const int c = wn * 64 + nt * 8 + ((lane & 3) << 1);
                *(float2*)(orow + c) = make_float2(acc[mt][nt][hh * 2], acc[mt][nt][hh * 2 + 1]);
            }
        }
    }
}

// ---------------- indices ----------------
__global__ void k5_idx(float* __restrict__ out_idx) {
    int i = blockIdx.x * blockDim.x + threadIdx.x;
    if (i < N_PIX) out_idx[i] = (float)(unsigned)(g_argmin[i] & 0xFFFFFFFFULL);
}

// ---------------- launcher ----------------
extern "C" void kernel_launch(void* const* d_in, const int* in_sizes, int n_in,
                              void* d_out, int out_size) {
    const float* x     = (const float*)d_in[0];
    const float* cb    = (const float*)d_in[1];
    const float* noise = (const float*)d_in[2];

    float* out     = (float*)d_out;
    float* out_q   = out;                                   // [16384, 256]
    float* out_enc = out + (size_t)N_PIX * D_DIM;           // [16384, 8192]
    float* out_idx = out_enc + (size_t)N_PIX * K_CODES;     // [16384]

    static bool attr_done = false;
    if (!attr_done) {
        cudaFuncSetAttribute(k_gemm1, cudaFuncAttributeMaxDynamicSharedMemorySize, 81920);
        cudaFuncSetAttribute(k_gemm2, cudaFuncAttributeMaxDynamicSharedMemorySize, 110592);
        attr_done = true;
    }

    k_prep<<<N_PIX / 8, 256>>>(x, 0);                                   // 1 (also inits argmin)
    k_prep<<<K_CODES / 8, 256>>>(cb, 1);                                // 2
    k_transpose<<<dim3(K_CODES / 32, D_DIM / 32), dim3(32, 8)>>>(cb);   // 3
    k_gemm1<<<dim3(K_CODES / 128, N_PIX / 128), 256, 81920>>>(noise, out_enc);  // 4 (ncu slot)
    k_softmax<<<N_PIX, 256>>>(out_enc);                                 // 5
    k_gemm2<<<N_PIX / 128, 256, 110592>>>(out_q);                       // 6
    k5_idx<<<N_PIX / 256, 256>>>(out_idx);                              // 7
}

// round 16
// speedup vs baseline: 1.0193x; 1.0193x over previous
#include <cuda_runtime.h>
#include <cuda_fp16.h>
#include <math_constants.h>
#include <cstdint>

#define N_PIX   16384
#define K_CODES 8192
#define D_DIM   256

// ---------------- scratch ----------------
__device__ float g_x2[N_PIX];
__device__ float g_c2[K_CODES];
__device__ unsigned long long g_argmin[N_PIX];
__device__ __half g_xs[2][N_PIX * D_DIM];                 // x hi/lo fp16
__device__ __half g_cs[2][K_CODES * D_DIM];               // cb hi/lo fp16
__device__ __half g_cbT[(size_t)D_DIM * K_CODES];         // cbT hi fp16
__device__ __half g_ench[(size_t)N_PIX * K_CODES];        // encodings hi fp16

// ---------------- PTX helpers (plain sm_80+) ----------------
__device__ __forceinline__ uint32_t smem_u32(const void* p) {
    uint32_t a;
    asm("{ .reg .u64 t; cvta.to.shared.u64 t, %1; cvt.u32.u64 %0, t; }" : "=r"(a) : "l"(p));
    return a;
}
#define CP16(sa, ga)  asm volatile("cp.async.cg.shared.global [%0], [%1], 16;" :: "r"(sa), "l"(ga) : "memory")
#define CPCOMMIT()    asm volatile("cp.async.commit_group;" ::: "memory")
#define CPWAIT0()     asm volatile("cp.async.wait_group 0;" ::: "memory")

#define LDSM4(r0, r1, r2, r3, a) asm volatile(                                   \
    "ldmatrix.sync.aligned.m8n8.x4.shared.b16 {%0,%1,%2,%3}, [%4];"              \
    : "=r"(r0), "=r"(r1), "=r"(r2), "=r"(r3) : "r"(a))

#define MMA(c, a, b) asm volatile(                                               \
    "mma.sync.aligned.m16n8k16.row.col.f32.f16.f16.f32 "                         \
    "{%0,%1,%2,%3}, {%4,%5,%6,%7}, {%8,%9}, {%0,%1,%2,%3};"                      \
    : "+f"((c)[0]), "+f"((c)[1]), "+f"((c)[2]), "+f"((c)[3])                     \
    : "r"((a)[0]), "r"((a)[1]), "r"((a)[2]), "r"((a)[3]),                        \
      "r"((b)[0]), "r"((b)[1]))

#define ROWB 80          // row stride 80B for 32-fp16 rows (conflict-free ldmatrix)
#define TILEB 10240      // one 128x32 fp16 tile
#define STAGE1 40960     // Ah|Am|Bh|Bm per stage (gemm1, 128x128 tile)
#define ROWB2 144        // 128 rows x 64 fp16, stride 144B (gemm2)
#define TILE2 18432      // one 128x64 fp16 tile (gemm2)

__device__ __forceinline__ uint32_t h2u(__half2 h) { return *reinterpret_cast<uint32_t*>(&h); }

// ---------------- prepass: fp16 hi/lo split + row norm (+argmin init for x) ----------------
__global__ __launch_bounds__(256)
void k_prep(const float* __restrict__ src, int which) {
    const int row = blockIdx.x * 8 + (threadIdx.x >> 5);
    const int lane = threadIdx.x & 31;
    const float* p = src + (size_t)row * D_DIM + lane * 8;
    float4 v0 = ((const float4*)p)[0], v1 = ((const float4*)p)[1];
    float f[8] = {v0.x, v0.y, v0.z, v0.w, v1.x, v1.y, v1.z, v1.w};
    __half hi[8]; float s = 0.f;
    uint32_t hw[4], mw[4];
#pragma unroll
    for (int t = 0; t < 8; t++) { hi[t] = __float2half_rn(f[t]); s = fmaf(f[t], f[t], s); }
#pragma unroll
    for (int t = 0; t < 4; t++) {
        hw[t] = h2u(__halves2half2(hi[2*t], hi[2*t+1]));
        mw[t] = h2u(__floats2half2_rn(f[2*t]   - __half2float(hi[2*t]),
                                      f[2*t+1] - __half2float(hi[2*t+1])));
    }
    size_t o = ((size_t)row * D_DIM + lane * 8);
    __half* H = which ? g_cs[0] : g_xs[0];
    __half* M = which ? g_cs[1] : g_xs[1];
    *(uint4*)(H + o) = make_uint4(hw[0], hw[1], hw[2], hw[3]);
    *(uint4*)(M + o) = make_uint4(mw[0], mw[1], mw[2], mw[3]);
#pragma unroll
    for (int o2 = 16; o2 > 0; o2 >>= 1) s += __shfl_xor_sync(0xffffffffu, s, o2);
    if (lane == 0) {
        (which ? g_c2 : g_x2)[row] = s;
        if (!which) g_argmin[row] = 0xFFFFFFFFFFFFFFFFULL;
    }
}

__global__ void k_transpose(const float* __restrict__ cb) {
    __shared__ float t[32][33];
    int k0 = blockIdx.x * 32, d0 = blockIdx.y * 32;
    int tx = threadIdx.x, ty = threadIdx.y;  // 32x8
#pragma unroll
    for (int i = 0; i < 32; i += 8)
        t[ty + i][tx] = cb[(size_t)(k0 + ty + i) * D_DIM + d0 + tx];
    __syncthreads();
#pragma unroll
    for (int i = 0; i < 32; i += 8)
        g_cbT[(size_t)(d0 + ty + i) * K_CODES + k0 + tx] = __float2half_rn(t[tx][ty + i]);
}

// ---------------- GEMM1: 128x128 tile, 8 warps (warp 64x32), 3-combo fp16 split ----------------
// Writes SHIFTED logits l' = noise + 2xc - c2 (x2 row-constant dropped; softmax is
// shift-invariant per row, and exp(l') is fp32-safe without max subtraction).
// Argmin key uses d'+64 (>0) = c2 - 2xc + 64: same ordering as true dist.
// dyn smem: 2 stages x [Ah|Am|Bh|Bm] x 10240B = 81920B -> 2 CTAs/SM
// Dead stage buffers recycled as smem noise cache (rows 0..79 / 80..127).
__global__ __launch_bounds__(256)
void k_gemm1(const float* __restrict__ noise, float* __restrict__ logits) {
    extern __shared__ __align__(16) char dyn[];
    __shared__ float c2s[128];
    __shared__ unsigned long long sMin[128];
    const uint32_t db = smem_u32(dyn);

    const int tid = threadIdx.x, lane = tid & 31, wid = tid >> 5;
    const int wm = wid >> 2, wn = wid & 3;
    const int rowBase = blockIdx.y << 7, colBase = blockIdx.x << 7;

    if (tid < 128) {
        c2s[tid] = g_c2[colBase + tid];
        sMin[tid] = 0xFFFFFFFFFFFFFFFFULL;
    }

    float acc[4][4][4];
#pragma unroll
    for (int a = 0; a < 4; a++)
#pragma unroll
        for (int b = 0; b < 4; b++)
#pragma unroll
            for (int c = 0; c < 4; c++) acc[a][b][c] = 0.f;

    const int r = tid >> 1, h = tid & 1;
    const uint32_t so = (uint32_t)(r * ROWB + h * 32);
    const float* ntile = noise + (size_t)rowBase * K_CODES + colBase;

    auto load_stage = [&](int s, int k0) {
        uint32_t base = db + s * STAGE1;
        size_t ao = (size_t)(rowBase + r) * D_DIM + k0 + h * 16;
        size_t bo = (size_t)(colBase + r) * D_DIM + k0 + h * 16;
        CP16(base + so, g_xs[0] + ao);                 CP16(base + so + 16, g_xs[0] + ao + 8);
        CP16(base + TILEB + so, g_xs[1] + ao);         CP16(base + TILEB + so + 16, g_xs[1] + ao + 8);
        CP16(base + 2*TILEB + so, g_cs[0] + bo);       CP16(base + 2*TILEB + so + 16, g_cs[0] + bo + 8);
        CP16(base + 3*TILEB + so, g_cs[1] + bo);       CP16(base + 3*TILEB + so + 16, g_cs[1] + bo + 8);
        CPCOMMIT();
    };

    load_stage(0, 0);
    for (int s = 0; s < 8; s++) {
        CPWAIT0();
        __syncthreads();
        if (s + 1 < 8) {
            load_stage((s + 1) & 1, (s + 1) << 5);
        } else {
            // prefetch noise rows 0..79 into buf0 (free since mma(6)); 10x16B per thread
#pragma unroll
            for (int i = 0; i < 10; i++) {
                uint32_t o = (uint32_t)(i * 256 + tid) * 16;      // 0..40944
                uint32_t rr = o >> 9, cc = o & 511;               // row, byte-col
                CP16(db + o, (const char*)ntile + (size_t)rr * (K_CODES * 4) + cc);
            }
            CPCOMMIT();
        }
        uint32_t base = db + (s & 1) * STAGE1;
        const uint32_t aH = base, aM = base + TILEB;
        const uint32_t bH = base + 2*TILEB, bM = bH + TILEB;
#pragma unroll
        for (int kk = 0; kk < 2; kk++) {
            uint32_t ah[4][4], am[4][4], bh[4][2], bm[4][2];
#pragma unroll
            for (int mt = 0; mt < 4; mt++) {
                uint32_t off = (uint32_t)((wm * 64 + mt * 16 + (lane & 15)) * ROWB
                                          + ((lane >> 4) << 4) + kk * 32);
                LDSM4(ah[mt][0], ah[mt][1], ah[mt][2], ah[mt][3], aH + off);
                LDSM4(am[mt][0], am[mt][1], am[mt][2], am[mt][3], aM + off);
            }
#pragma unroll
            for (int n2 = 0; n2 < 2; n2++) {
                uint32_t off = (uint32_t)((wn * 32 + n2 * 16 + (lane & 7) + ((lane >> 4) << 3)) * ROWB
                                          + (((lane >> 3) & 1) << 4) + kk * 32);
                LDSM4(bh[2*n2][0], bh[2*n2][1], bh[2*n2+1][0], bh[2*n2+1][1], bH + off);
                LDSM4(bm[2*n2][0], bm[2*n2][1], bm[2*n2+1][0], bm[2*n2+1][1], bM + off);
            }
#pragma unroll
            for (int mt = 0; mt < 4; mt++)
#pragma unroll
                for (int nt = 0; nt < 4; nt++) {
                    MMA(acc[mt][nt], ah[mt], bh[nt]);
                    MMA(acc[mt][nt], am[mt], bh[nt]);
                    MMA(acc[mt][nt], ah[mt], bm[nt]);
                }
        }
    }

    CPWAIT0();          // my noise part1 arrived
    __syncthreads();    // everyone's part1 visible; everyone done with mma(7) -> buf1 free

    // prefetch noise rows 80..127 into buf1 (6x16B per thread), overlapped with pass A
#pragma unroll
    for (int i = 0; i < 6; i++) {
        uint32_t o = (uint32_t)(i * 256 + tid) * 16;              // 0..24560
        uint32_t rr = 80 + (o >> 9), cc = o & 511;
        CP16(db + STAGE1 + o, (const char*)ntile + (size_t)rr * (K_CODES * 4) + cc);
    }
    CPCOMMIT();

    // epilogue: d' = c2 - 2xc ; logit' = noise - d' ; argmin key = d' + 64 (positive)
    auto epi_group = [&](int mt, int hh) {
        const int rr = wm * 64 + mt * 16 + (lane >> 2) + hh * 8;
        const int grow = rowBase + rr;
        unsigned long long best = 0xFFFFFFFFFFFFFFFFULL;
        float* lrow = logits + (size_t)grow * K_CODES + colBase;
        const uint32_t nbase = (rr < 80) ? (db + (uint32_t)rr * 512)
                                         : (db + STAGE1 + (uint32_t)(rr - 80) * 512);
#pragma unroll
        for (int nt = 0; nt < 4; nt++) {
            const int c = wn * 32 + nt * 8 + ((lane & 3) << 1);
            float2 nz;
            asm volatile("ld.shared.v2.f32 {%0,%1}, [%2];" : "=f"(nz.x), "=f"(nz.y)
                         : "r"(nbase + (uint32_t)c * 4));
            const float d0 = fmaf(-2.f, acc[mt][nt][hh * 2 + 0], c2s[c]);
            const float d1 = fmaf(-2.f, acc[mt][nt][hh * 2 + 1], c2s[c + 1]);
            *(float2*)(lrow + c) = make_float2(nz.x - d0, nz.y - d1);
            const float k0f = d0 + 64.0f, k1f = d1 + 64.0f;   // > 0, ordering == dist
            unsigned long long p0 = ((unsigned long long)__float_as_uint(k0f) << 32) | (unsigned)(colBase + c);
            unsigned long long p1 = ((unsigned long long)__float_as_uint(k1f) << 32) | (unsigned)(colBase + c + 1);
            if (p1 < p0) p0 = p1;
            if (p0 < best) best = p0;
        }
        atomicMin(&sMin[rr], best);
    };

    // pass A: rows < 80 -> wm==0: all mt ; wm==1: mt==0 only
    if (wm == 0) {
#pragma unroll
        for (int mt = 0; mt < 4; mt++) { epi_group(mt, 0); epi_group(mt, 1); }
    } else {
        epi_group(0, 0); epi_group(0, 1);
    }

    CPWAIT0();          // my noise part2 arrived
    __syncthreads();    // everyone's part2 visible

    // pass B: rows 80..127 -> wm==1, mt 1..3
    if (wm == 1) {
#pragma unroll
        for (int mt = 1; mt < 4; mt++) { epi_group(mt, 0); epi_group(mt, 1); }
    }

    __syncthreads();
    if (tid < 128) atomicMin(&g_argmin[rowBase + tid], sMin[tid]);
}

// ---------------- softmax: shift-safe, NO max pass (2 smem passes) ----------------
// logits hold l' = noise + 2xc - c2 in [~-15, ~31]: exp fp32-safe, sum <= 8192*e^31.
__global__ __launch_bounds__(256)
void k_softmax(float* __restrict__ logits) {
    __shared__ float buf[K_CODES];
    __shared__ float red[8];
    const int row = blockIdx.x, t = threadIdx.x, lane = t & 31, w = t >> 5;
    float* p = logits + (size_t)row * K_CODES;

    float s0 = 0.f, s1 = 0.f, s2 = 0.f, s3 = 0.f;
    for (int c = t * 4; c < K_CODES; c += 1024) {
        float4 v = *(const float4*)(p + c);
        v.x = __expf(v.x); v.y = __expf(v.y);
        v.z = __expf(v.z); v.w = __expf(v.w);
        *(float4*)(buf + c) = v;
        s0 += v.x; s1 += v.y; s2 += v.z; s3 += v.w;
    }
    float s = (s0 + s1) + (s2 + s3);
#pragma unroll
    for (int o = 16; o > 0; o >>= 1) s += __shfl_xor_sync(0xffffffffu, s, o);
    if (lane == 0) red[w] = s;
    __syncthreads();
    const float inv = 1.0f / (((red[0] + red[1]) + (red[2] + red[3]))
                            + ((red[4] + red[5]) + (red[6] + red[7])));
    for (int c = t * 4; c < K_CODES; c += 1024) {
        float4 v = *(const float4*)(buf + c);
        v.x *= inv; v.y *= inv; v.z *= inv; v.w *= inv;
        *(float4*)(p + c) = v;
        *(uint2*)(g_ench + (size_t)row * K_CODES + c) =
            make_uint2(h2u(__floats2half2_rn(v.x, v.y)), h2u(__floats2half2_rn(v.z, v.w)));
    }
}

// ---------------- GEMM2: quantized = enc_h @ cbT_h (single-combo fp16), 1 sync/stage ----------------
// dyn smem: 2 stages x [A|B] x 18432B = 73728B ; grid (2, 128) -> one wave at 2 CTAs/SM
__global__ __launch_bounds__(256)
void k_gemm2(float* __restrict__ outq) {
    extern __shared__ __align__(16) char dyn[];
    const uint32_t db = smem_u32(dyn);

    const int tid = threadIdx.x, lane = tid & 31, wid = tid >> 5;
    const int wm = wid >> 2, wn = wid & 3;
    const int rowBase = blockIdx.y << 7, dBase = blockIdx.x << 7;

    float acc[4][4][4];
#pragma unroll
    for (int a = 0; a < 4; a++)
#pragma unroll
        for (int b = 0; b < 4; b++)
#pragma unroll
            for (int c = 0; c < 4; c++) acc[a][b][c] = 0.f;

    const int r = tid >> 1, h = tid & 1;
    const uint32_t so = (uint32_t)(r * ROWB2 + h * 64);

    auto load_stage = [&](int s, int k0) {
        uint32_t base = db + s * (2 * TILE2);
        size_t ao = (size_t)(rowBase + r) * K_CODES + k0 + h * 32;
        size_t bo = (size_t)(dBase + r) * K_CODES + k0 + h * 32;
        CP16(base + so,      g_ench + ao);      CP16(base + so + 16, g_ench + ao + 8);
        CP16(base + so + 32, g_ench + ao + 16); CP16(base + so + 48, g_ench + ao + 24);
        uint32_t bb = base + TILE2;
        CP16(bb + so,      g_cbT + bo);         CP16(bb + so + 16, g_cbT + bo + 8);
        CP16(bb + so + 32, g_cbT + bo + 16);    CP16(bb + so + 48, g_cbT + bo + 24);
        CPCOMMIT();
    };

    load_stage(0, 0);
    for (int s = 0; s < 128; s++) {
        CPWAIT0();
        __syncthreads();
        if (s + 1 < 128) load_stage((s + 1) & 1, (s + 1) << 6);
        uint32_t base = db + (s & 1) * (2 * TILE2);
        const uint32_t aB = base, bB = base + TILE2;
#pragma unroll
        for (int kk = 0; kk < 4; kk++) {
            uint32_t af[4][4], bf[4][2];
#pragma unroll
            for (int mt = 0; mt < 4; mt++) {
                uint32_t off = (uint32_t)((wm * 64 + mt * 16 + (lane & 15)) * ROWB2
                                          + ((lane >> 4) << 4) + kk * 32);
                LDSM4(af[mt][0], af[mt][1], af[mt][2], af[mt][3], aB + off);
            }
#pragma unroll
            for (int n2 = 0; n2 < 2; n2++) {
                uint32_t off = (uint32_t)((wn * 32 + n2 * 16 + (lane & 7) + ((lane >> 4) << 3)) * ROWB2
                                          + (((lane >> 3) & 1) << 4) + kk * 32);
                LDSM4(bf[2*n2][0], bf[2*n2][1], bf[2*n2+1][0], bf[2*n2+1][1], bB + off);
            }
#pragma unroll
            for (int mt = 0; mt < 4; mt++)
#pragma unroll
                for (int nt = 0; nt < 4; nt++)
                    MMA(acc[mt][nt], af[mt], bf[nt]);
        }
    }

#pragma unroll
    for (int mt = 0; mt < 4; mt++) {
#pragma unroll
        for (int hh = 0; hh < 2; hh++) {
            const int grow = rowBase + wm * 64 + mt * 16 + (lane >> 2) + hh * 8;
            float* orow = outq + (size_t)grow * D_DIM + dBase;
#pragma unroll
            for (int nt = 0; nt < 4; nt++) {
                const int c = wn * 32 + nt * 8 + ((lane & 3) << 1);
                *(float2*)(orow + c) = make_float2(acc[mt][nt][hh * 2], acc[mt][nt][hh * 2 + 1]);
            }
        }
    }
}

// ---------------- indices ----------------
__global__ void k5_idx(float* __restrict__ out_idx) {
    int i = blockIdx.x * blockDim.x + threadIdx.x;
    if (i < N_PIX) out_idx[i] = (float)(unsigned)(g_argmin[i] & 0xFFFFFFFFULL);
}

// ---------------- launcher ----------------
extern "C" void kernel_launch(void* const* d_in, const int* in_sizes, int n_in,
                              void* d_out, int out_size) {
    const float* x     = (const float*)d_in[0];
    const float* cb    = (const float*)d_in[1];
    const float* noise = (const float*)d_in[2];

    float* out     = (float*)d_out;
    float* out_q   = out;                                   // [16384, 256]
    float* out_enc = out + (size_t)N_PIX * D_DIM;           // [16384, 8192]
    float* out_idx = out_enc + (size_t)N_PIX * K_CODES;     // [16384]

    static bool attr_done = false;
    if (!attr_done) {
        cudaFuncSetAttribute(k_gemm1, cudaFuncAttributeMaxDynamicSharedMemorySize, 81920);
        cudaFuncSetAttribute(k_gemm2, cudaFuncAttributeMaxDynamicSharedMemorySize, 73728);
        attr_done = true;
    }

    k_prep<<<N_PIX / 8, 256>>>(x, 0);                                   // 1 (also inits argmin)
    k_prep<<<K_CODES / 8, 256>>>(cb, 1);                                // 2
    k_transpose<<<dim3(K_CODES / 32, D_DIM / 32), dim3(32, 8)>>>(cb);   // 3
    k_gemm1<<<dim3(K_CODES / 128, N_PIX / 128), 256, 81920>>>(noise, out_enc);  // 4 (ncu slot)
    k_softmax<<<N_PIX, 256>>>(out_enc);                                 // 5
    k_gemm2<<<dim3(D_DIM / 128, N_PIX / 128), 256, 73728>>>(out_q);     // 6
    k5_idx<<<N_PIX / 256, 256>>>(out_idx);                              // 7
}

// round 17
// speedup vs baseline: 1.0382x; 1.0185x over previous
#include <cuda_runtime.h>
#include <cuda_fp16.h>
#include <math_constants.h>
#include <cstdint>

#define N_PIX   16384
#define K_CODES 8192
#define D_DIM   256

// ---------------- scratch ----------------
__device__ float g_x2[N_PIX];
__device__ float g_c2[K_CODES];
__device__ unsigned long long g_argmin[N_PIX];
__device__ __half g_xs[2][N_PIX * D_DIM];                 // x hi/lo fp16
__device__ __half g_cs[2][K_CODES * D_DIM];               // cb hi/lo fp16
__device__ __half g_cbT[(size_t)D_DIM * K_CODES];         // cbT hi fp16
__device__ __half g_ench[(size_t)N_PIX * K_CODES];        // encodings hi fp16

// ---------------- PTX helpers (plain sm_80+) ----------------
__device__ __forceinline__ uint32_t smem_u32(const void* p) {
    uint32_t a;
    asm("{ .reg .u64 t; cvta.to.shared.u64 t, %1; cvt.u32.u64 %0, t; }" : "=r"(a) : "l"(p));
    return a;
}
#define CP16(sa, ga)  asm volatile("cp.async.cg.shared.global [%0], [%1], 16;" :: "r"(sa), "l"(ga) : "memory")
#define CPCOMMIT()    asm volatile("cp.async.commit_group;" ::: "memory")
#define CPWAIT0()     asm volatile("cp.async.wait_group 0;" ::: "memory")

#define LDSM4(r0, r1, r2, r3, a) asm volatile(                                   \
    "ldmatrix.sync.aligned.m8n8.x4.shared.b16 {%0,%1,%2,%3}, [%4];"              \
    : "=r"(r0), "=r"(r1), "=r"(r2), "=r"(r3) : "r"(a))

#define MMA(c, a, b) asm volatile(                                               \
    "mma.sync.aligned.m16n8k16.row.col.f32.f16.f16.f32 "                         \
    "{%0,%1,%2,%3}, {%4,%5,%6,%7}, {%8,%9}, {%0,%1,%2,%3};"                      \
    : "+f"((c)[0]), "+f"((c)[1]), "+f"((c)[2]), "+f"((c)[3])                     \
    : "r"((a)[0]), "r"((a)[1]), "r"((a)[2]), "r"((a)[3]),                        \
      "r"((b)[0]), "r"((b)[1]))

#define ROWB 80          // row stride 80B for 32-fp16 rows (conflict-free ldmatrix)
#define TILEB 10240      // one 128x32 fp16 tile
#define STAGE1 40960     // Ah|Am|Bh|Bm per stage (gemm1, 128x128 tile)
#define ROWB2 144        // 128 rows x 64 fp16, stride 144B (gemm2)
#define TILE2 18432      // one 128x64 fp16 tile (gemm2)

__device__ __forceinline__ uint32_t h2u(__half2 h) { return *reinterpret_cast<uint32_t*>(&h); }

// ---------------- prepass: fp16 hi/lo split + row norm (+argmin init for x) ----------------
__global__ __launch_bounds__(256)
void k_prep(const float* __restrict__ src, int which) {
    const int row = blockIdx.x * 8 + (threadIdx.x >> 5);
    const int lane = threadIdx.x & 31;
    const float* p = src + (size_t)row * D_DIM + lane * 8;
    float4 v0 = ((const float4*)p)[0], v1 = ((const float4*)p)[1];
    float f[8] = {v0.x, v0.y, v0.z, v0.w, v1.x, v1.y, v1.z, v1.w};
    __half hi[8]; float s = 0.f;
    uint32_t hw[4], mw[4];
#pragma unroll
    for (int t = 0; t < 8; t++) { hi[t] = __float2half_rn(f[t]); s = fmaf(f[t], f[t], s); }
#pragma unroll
    for (int t = 0; t < 4; t++) {
        hw[t] = h2u(__halves2half2(hi[2*t], hi[2*t+1]));
        mw[t] = h2u(__floats2half2_rn(f[2*t]   - __half2float(hi[2*t]),
                                      f[2*t+1] - __half2float(hi[2*t+1])));
    }
    size_t o = ((size_t)row * D_DIM + lane * 8);
    __half* H = which ? g_cs[0] : g_xs[0];
    __half* M = which ? g_cs[1] : g_xs[1];
    *(uint4*)(H + o) = make_uint4(hw[0], hw[1], hw[2], hw[3]);
    *(uint4*)(M + o) = make_uint4(mw[0], mw[1], mw[2], mw[3]);
#pragma unroll
    for (int o2 = 16; o2 > 0; o2 >>= 1) s += __shfl_xor_sync(0xffffffffu, s, o2);
    if (lane == 0) {
        (which ? g_c2 : g_x2)[row] = s;
        if (!which) g_argmin[row] = 0xFFFFFFFFFFFFFFFFULL;
    }
}

__global__ void k_transpose(const float* __restrict__ cb) {
    __shared__ float t[32][33];
    int k0 = blockIdx.x * 32, d0 = blockIdx.y * 32;
    int tx = threadIdx.x, ty = threadIdx.y;  // 32x8
#pragma unroll
    for (int i = 0; i < 32; i += 8)
        t[ty + i][tx] = cb[(size_t)(k0 + ty + i) * D_DIM + d0 + tx];
    __syncthreads();
#pragma unroll
    for (int i = 0; i < 32; i += 8)
        g_cbT[(size_t)(d0 + ty + i) * K_CODES + k0 + tx] = __float2half_rn(t[tx][ty + i]);
}

// ---------------- GEMM1: 128x128 tile, 8 warps (warp 64x32), 3-combo fp16 split ----------------
// Writes SHIFTED logits l' = noise + 2xc - c2 (softmax is shift-invariant per row;
// exp(l') is fp32-safe without max subtraction).
// Argmin key uses d'+64 (>0) = c2 - 2xc + 64: same ordering as true dist.
// dyn smem: 2 stages x [Ah|Am|Bh|Bm] x 10240B = 81920B -> 2 CTAs/SM
// Dead stage buffers recycled as smem noise cache (rows 0..79 / 80..127).
__global__ __launch_bounds__(256)
void k_gemm1(const float* __restrict__ noise, float* __restrict__ logits) {
    extern __shared__ __align__(16) char dyn[];
    __shared__ float c2s[128];
    __shared__ unsigned long long sMin[128];
    const uint32_t db = smem_u32(dyn);

    const int tid = threadIdx.x, lane = tid & 31, wid = tid >> 5;
    const int wm = wid >> 2, wn = wid & 3;
    const int rowBase = blockIdx.y << 7, colBase = blockIdx.x << 7;

    if (tid < 128) {
        c2s[tid] = g_c2[colBase + tid];
        sMin[tid] = 0xFFFFFFFFFFFFFFFFULL;
    }

    float acc[4][4][4];
#pragma unroll
    for (int a = 0; a < 4; a++)
#pragma unroll
        for (int b = 0; b < 4; b++)
#pragma unroll
            for (int c = 0; c < 4; c++) acc[a][b][c] = 0.f;

    const int r = tid >> 1, h = tid & 1;
    const uint32_t so = (uint32_t)(r * ROWB + h * 32);
    const float* ntile = noise + (size_t)rowBase * K_CODES + colBase;

    auto load_stage = [&](int s, int k0) {
        uint32_t base = db + s * STAGE1;
        size_t ao = (size_t)(rowBase + r) * D_DIM + k0 + h * 16;
        size_t bo = (size_t)(colBase + r) * D_DIM + k0 + h * 16;
        CP16(base + so, g_xs[0] + ao);                 CP16(base + so + 16, g_xs[0] + ao + 8);
        CP16(base + TILEB + so, g_xs[1] + ao);         CP16(base + TILEB + so + 16, g_xs[1] + ao + 8);
        CP16(base + 2*TILEB + so, g_cs[0] + bo);       CP16(base + 2*TILEB + so + 16, g_cs[0] + bo + 8);
        CP16(base + 3*TILEB + so, g_cs[1] + bo);       CP16(base + 3*TILEB + so + 16, g_cs[1] + bo + 8);
        CPCOMMIT();
    };

    load_stage(0, 0);
    for (int s = 0; s < 8; s++) {
        CPWAIT0();
        __syncthreads();
        if (s + 1 < 8) {
            load_stage((s + 1) & 1, (s + 1) << 5);
        } else {
            // prefetch noise rows 0..79 into buf0 (free since mma(6)); 10x16B per thread
#pragma unroll
            for (int i = 0; i < 10; i++) {
                uint32_t o = (uint32_t)(i * 256 + tid) * 16;      // 0..40944
                uint32_t rr = o >> 9, cc = o & 511;               // row, byte-col
                CP16(db + o, (const char*)ntile + (size_t)rr * (K_CODES * 4) + cc);
            }
            CPCOMMIT();
        }
        uint32_t base = db + (s & 1) * STAGE1;
        const uint32_t aH = base, aM = base + TILEB;
        const uint32_t bH = base + 2*TILEB, bM = bH + TILEB;
#pragma unroll
        for (int kk = 0; kk < 2; kk++) {
            uint32_t ah[4][4], am[4][4], bh[4][2], bm[4][2];
#pragma unroll
            for (int mt = 0; mt < 4; mt++) {
                uint32_t off = (uint32_t)((wm * 64 + mt * 16 + (lane & 15)) * ROWB
                                          + ((lane >> 4) << 4) + kk * 32);
                LDSM4(ah[mt][0], ah[mt][1], ah[mt][2], ah[mt][3], aH + off);
                LDSM4(am[mt][0], am[mt][1], am[mt][2], am[mt][3], aM + off);
            }
#pragma unroll
            for (int n2 = 0; n2 < 2; n2++) {
                uint32_t off = (uint32_t)((wn * 32 + n2 * 16 + (lane & 7) + ((lane >> 4) << 3)) * ROWB
                                          + (((lane >> 3) & 1) << 4) + kk * 32);
                LDSM4(bh[2*n2][0], bh[2*n2][1], bh[2*n2+1][0], bh[2*n2+1][1], bH + off);
                LDSM4(bm[2*n2][0], bm[2*n2][1], bm[2*n2+1][0], bm[2*n2+1][1], bM + off);
            }
#pragma unroll
            for (int mt = 0; mt < 4; mt++)
#pragma unroll
                for (int nt = 0; nt < 4; nt++) {
                    MMA(acc[mt][nt], ah[mt], bh[nt]);
                    MMA(acc[mt][nt], am[mt], bh[nt]);
                    MMA(acc[mt][nt], ah[mt], bm[nt]);
                }
        }
    }

    CPWAIT0();          // my noise part1 arrived
    __syncthreads();    // everyone's part1 visible; everyone done with mma(7) -> buf1 free

    // prefetch noise rows 80..127 into buf1 (6x16B per thread), overlapped with pass A
#pragma unroll
    for (int i = 0; i < 6; i++) {
        uint32_t o = (uint32_t)(i * 256 + tid) * 16;              // 0..24560
        uint32_t rr = 80 + (o >> 9), cc = o & 511;
        CP16(db + STAGE1 + o, (const char*)ntile + (size_t)rr * (K_CODES * 4) + cc);
    }
    CPCOMMIT();

    // epilogue: d' = c2 - 2xc ; logit' = noise - d' ; argmin key = d' + 64 (positive)
    auto epi_group = [&](int mt, int hh) {
        const int rr = wm * 64 + mt * 16 + (lane >> 2) + hh * 8;
        const int grow = rowBase + rr;
        unsigned long long best = 0xFFFFFFFFFFFFFFFFULL;
        float* lrow = logits + (size_t)grow * K_CODES + colBase;
        const uint32_t nbase = (rr < 80) ? (db + (uint32_t)rr * 512)
                                         : (db + STAGE1 + (uint32_t)(rr - 80) * 512);
#pragma unroll
        for (int nt = 0; nt < 4; nt++) {
            const int c = wn * 32 + nt * 8 + ((lane & 3) << 1);
            float2 nz;
            asm volatile("ld.shared.v2.f32 {%0,%1}, [%2];" : "=f"(nz.x), "=f"(nz.y)
                         : "r"(nbase + (uint32_t)c * 4));
            const float d0 = fmaf(-2.f, acc[mt][nt][hh * 2 + 0], c2s[c]);
            const float d1 = fmaf(-2.f, acc[mt][nt][hh * 2 + 1], c2s[c + 1]);
            *(float2*)(lrow + c) = make_float2(nz.x - d0, nz.y - d1);
            const float k0f = d0 + 64.0f, k1f = d1 + 64.0f;   // > 0, ordering == dist
            unsigned long long p0 = ((unsigned long long)__float_as_uint(k0f) << 32) | (unsigned)(colBase + c);
            unsigned long long p1 = ((unsigned long long)__float_as_uint(k1f) << 32) | (unsigned)(colBase + c + 1);
            if (p1 < p0) p0 = p1;
            if (p0 < best) best = p0;
        }
        atomicMin(&sMin[rr], best);
    };

    // pass A: rows < 80 -> wm==0: all mt ; wm==1: mt==0 only
    if (wm == 0) {
#pragma unroll
        for (int mt = 0; mt < 4; mt++) { epi_group(mt, 0); epi_group(mt, 1); }
    } else {
        epi_group(0, 0); epi_group(0, 1);
    }

    CPWAIT0();          // my noise part2 arrived
    __syncthreads();    // everyone's part2 visible

    // pass B: rows 80..127 -> wm==1, mt 1..3
    if (wm == 1) {
#pragma unroll
        for (int mt = 1; mt < 4; mt++) { epi_group(mt, 0); epi_group(mt, 1); }
    }

    __syncthreads();
    if (tid < 128) atomicMin(&g_argmin[rowBase + tid], sMin[tid]);
}

// ---------------- softmax: register-resident, no max pass, no smem buffer ----------------
// logits hold l' = noise + 2xc - c2 in [~-15, ~31]: exp fp32-safe, sum <= 8192*e^31.
// Each thread owns 8 float4 (32 values) of the row in registers.
__global__ __launch_bounds__(256)
void k_softmax(float* __restrict__ logits) {
    __shared__ float red[8];
    const int row = blockIdx.x, t = threadIdx.x, lane = t & 31, w = t >> 5;
    float4* p = (float4*)(logits + (size_t)row * K_CODES);   // 2048 float4 per row
    uint2* e = (uint2*)(g_ench + (size_t)row * K_CODES);

    float4 v[8];
    float s = 0.f;
#pragma unroll
    for (int i = 0; i < 8; i++) {
        float4 x = p[t + i * 256];
        x.x = __expf(x.x); x.y = __expf(x.y);
        x.z = __expf(x.z); x.w = __expf(x.w);
        v[i] = x;
        s += (x.x + x.y) + (x.z + x.w);
    }
#pragma unroll
    for (int o = 16; o > 0; o >>= 1) s += __shfl_xor_sync(0xffffffffu, s, o);
    if (lane == 0) red[w] = s;
    __syncthreads();
    const float inv = 1.0f / (((red[0] + red[1]) + (red[2] + red[3]))
                            + ((red[4] + red[5]) + (red[6] + red[7])));
#pragma unroll
    for (int i = 0; i < 8; i++) {
        float4 x = v[i];
        x.x *= inv; x.y *= inv; x.z *= inv; x.w *= inv;
        p[t + i * 256] = x;
        e[t + i * 256] = make_uint2(h2u(__floats2half2_rn(x.x, x.y)),
                                    h2u(__floats2half2_rn(x.z, x.w)));
    }
}

// ---------------- GEMM2: quantized = enc_h @ cbT_h (single-combo fp16), 1 sync/stage ----------------
// dyn smem: 2 stages x [A|B] x 18432B = 73728B ; grid (2, 128) -> one wave at 2 CTAs/SM
__global__ __launch_bounds__(256)
void k_gemm2(float* __restrict__ outq) {
    extern __shared__ __align__(16) char dyn[];
    const uint32_t db = smem_u32(dyn);

    const int tid = threadIdx.x, lane = tid & 31, wid = tid >> 5;
    const int wm = wid >> 2, wn = wid & 3;
    const int rowBase = blockIdx.y << 7, dBase = blockIdx.x << 7;

    float acc[4][4][4];
#pragma unroll
    for (int a = 0; a < 4; a++)
#pragma unroll
        for (int b = 0; b < 4; b++)
#pragma unroll
            for (int c = 0; c < 4; c++) acc[a][b][c] = 0.f;

    const int r = tid >> 1, h = tid & 1;
    const uint32_t so = (uint32_t)(r * ROWB2 + h * 64);

    auto load_stage = [&](int s, int k0) {
        uint32_t base = db + s * (2 * TILE2);
        size_t ao = (size_t)(rowBase + r) * K_CODES + k0 + h * 32;
        size_t bo = (size_t)(dBase + r) * K_CODES + k0 + h * 32;
        CP16(base + so,      g_ench + ao);      CP16(base + so + 16, g_ench + ao + 8);
        CP16(base + so + 32, g_ench + ao + 16); CP16(base + so + 48, g_ench + ao + 24);
        uint32_t bb = base + TILE2;
        CP16(bb + so,      g_cbT + bo);         CP16(bb + so + 16, g_cbT + bo + 8);
        CP16(bb + so + 32, g_cbT + bo + 16);    CP16(bb + so + 48, g_cbT + bo + 24);
        CPCOMMIT();
    };

    load_stage(0, 0);
    for (int s = 0; s < 128; s++) {
        CPWAIT0();
        __syncthreads();
        if (s + 1 < 128) load_stage((s + 1) & 1, (s + 1) << 6);
        uint32_t base = db + (s & 1) * (2 * TILE2);
        const uint32_t aB = base, bB = base + TILE2;
#pragma unroll
        for (int kk = 0; kk < 4; kk++) {
            uint32_t af[4][4], bf[4][2];
#pragma unroll
            for (int mt = 0; mt < 4; mt++) {
                uint32_t off = (uint32_t)((wm * 64 + mt * 16 + (lane & 15)) * ROWB2
                                          + ((lane >> 4) << 4) + kk * 32);
                LDSM4(af[mt][0], af[mt][1], af[mt][2], af[mt][3], aB + off);
            }
#pragma unroll
            for (int n2 = 0; n2 < 2; n2++) {
                uint32_t off = (uint32_t)((wn * 32 + n2 * 16 + (lane & 7) + ((lane >> 4) << 3)) * ROWB2
                                          + (((lane >> 3) & 1) << 4) + kk * 32);
                LDSM4(bf[2*n2][0], bf[2*n2][1], bf[2*n2+1][0], bf[2*n2+1][1], bB + off);
            }
#pragma unroll
            for (int mt = 0; mt < 4; mt++)
#pragma unroll
                for (int nt = 0; nt < 4; nt++)
                    MMA(acc[mt][nt], af[mt], bf[nt]);
        }
    }

#pragma unroll
    for (int mt = 0; mt < 4; mt++) {
#pragma unroll
        for (int hh = 0; hh < 2; hh++) {
            const int grow = rowBase + wm * 64 + mt * 16 + (lane >> 2) + hh * 8;
            float* orow = outq + (size_t)grow * D_DIM + dBase;
#pragma unroll
            for (int nt = 0; nt < 4; nt++) {
                const int c = wn * 32 + nt * 8 + ((lane & 3) << 1);
                *(float2*)(orow + c) = make_float2(acc[mt][nt][hh * 2], acc[mt][nt][hh * 2 + 1]);
            }
        }
    }
}

// ---------------- indices ----------------
__global__ void k5_idx(float* __restrict__ out_idx) {
    int i = blockIdx.x * blockDim.x + threadIdx.x;
    if (i < N_PIX) out_idx[i] = (float)(unsigned)(g_argmin[i] & 0xFFFFFFFFULL);
}

// ---------------- launcher ----------------
extern "C" void kernel_launch(void* const* d_in, const int* in_sizes, int n_in,
                              void* d_out, int out_size) {
    const float* x     = (const float*)d_in[0];
    const float* cb    = (const float*)d_in[1];
    const float* noise = (const float*)d_in[2];

    float* out     = (float*)d_out;
    float* out_q   = out;                                   // [16384, 256]
    float* out_enc = out + (size_t)N_PIX * D_DIM;           // [16384, 8192]
    float* out_idx = out_enc + (size_t)N_PIX * K_CODES;     // [16384]

    static bool attr_done = false;
    if (!attr_done) {
        cudaFuncSetAttribute(k_gemm1, cudaFuncAttributeMaxDynamicSharedMemorySize, 81920);
        cudaFuncSetAttribute(k_gemm2, cudaFuncAttributeMaxDynamicSharedMemorySize, 73728);
        attr_done = true;
    }

    k_prep<<<N_PIX / 8, 256>>>(x, 0);                                   // 1 (also inits argmin)
    k_prep<<<K_CODES / 8, 256>>>(cb, 1);                                // 2
    k_transpose<<<dim3(K_CODES / 32, D_DIM / 32), dim3(32, 8)>>>(cb);   // 3
    k_gemm1<<<dim3(K_CODES / 128, N_PIX / 128), 256, 81920>>>(noise, out_enc);  // 4 (ncu slot)
    k_softmax<<<N_PIX, 256>>>(out_enc);                                 // 5
    k_gemm2<<<dim3(D_DIM / 128, N_PIX / 128), 256, 73728>>>(out_q);     // 6
    k5_idx<<<N_PIX / 256, 256>>>(out_idx);                              // 7
}